// round 4
// baseline (speedup 1.0000x reference)
#include <cuda_runtime.h>
#include <math_constants.h>

// MAM dense: C[n,j] = max_k(x[n,k]*w[j,k]) + min_k(x[n,k]*w[j,k]) + bias[j]
// x: [2048, 512] f32, w: [256, 512] f32, bias: [256] f32, out: [2048, 256] f32
//
// R4: persistent warp-scheduled kernel.
//  - Grid = 148 CTAs x 128 thr -> 1 CTA/SM, 1 warp/SMSP (structural SMSP balance).
//  - 4096 warp-tiles of 16n x 8j, full K=512; warp g takes tiles g, g+592, ...
//    -> 7v6 tiles/warp = +1.2% over the alu-pipe floor.
//  - Thread tile 2n x 2j: 16 B smem per k for 4 FMUL + 8 FMNMX (2x reuse vs R3,
//    halves the L1 pressure that bound R3 at 77%).
//  - Warp-private double-buffered smem, no __syncthreads, 1 __syncwarp/chunk.

constexpr int IN_F  = 512;
constexpr int OUT_F = 256;
constexpr int NROWS = 2048;

constexpr int GRID    = 148;
constexpr int THREADS = 128;                      // 4 warps
constexpr int NWARP   = GRID * (THREADS / 32);    // 592

constexpr int TN = 16;                            // warp tile n
constexpr int TJ = 8;                             // warp tile j
constexpr int KB = 32;                            // k-chunk
constexpr int NCH = IN_F / KB;                    // 16
constexpr int TILES_J = OUT_F / TJ;               // 32
constexpr int NTILES  = (NROWS / TN) * TILES_J;   // 4096

constexpr int XLD = 18;  // xs row stride (even -> LDS.64 aligned; padded)
constexpr int WLD = 10;  // ws row stride

__global__ __launch_bounds__(THREADS, 1)
void mam_kernel(const float* __restrict__ x,
                const float* __restrict__ w,
                const float* __restrict__ bias,
                float* __restrict__ out)
{
    // Warp-private double buffers: [warp][buf][k][row]
    __shared__ __align__(16) float xs[4][2][KB][XLD];
    __shared__ __align__(16) float ws[4][2][KB][WLD];

    const int lane = threadIdx.x & 31;
    const int wid  = threadIdx.x >> 5;
    const int gw   = blockIdx.x * 4 + wid;

    float (*xsw)[KB][XLD] = xs[wid];
    float (*wsw)[KB][WLD] = ws[wid];

    // Compute mapping: 8 tn-groups x 4 tj-groups, 2x2 outputs each.
    const int tn2 = (lane >> 2) * 2;   // n offset within tile
    const int tj2 = (lane & 3) * 2;    // j offset within tile

    // Loader mapping (both tensors): row-sub = lane>>3, k-quad = (lane&7)*4.
    const int lrow = lane >> 3;        // 0..3
    const int lkq  = (lane & 7) * 4;   // 0,4,...,28

    const float NEG_INF = -CUDART_INF_F;

    for (int t = gw; t < NTILES; t += NWARP) {
        const int j0 = (t & (TILES_J - 1)) * TJ;
        const int n0 = (t / TILES_J) * TN;

        float mx00 = NEG_INF, mx01 = NEG_INF, mx10 = NEG_INF, mx11 = NEG_INF;
        float mn00 = -NEG_INF, mn01 = -NEG_INF, mn10 = -NEG_INF, mn11 = -NEG_INF;

        const float* xb = &x[n0 * IN_F + lkq];
        const float* wb = &w[j0 * IN_F + lkq];

        float4 xv[4], wv[2];
        // LDG chunk 0
#pragma unroll
        for (int i = 0; i < 4; i++)
            xv[i] = *reinterpret_cast<const float4*>(&xb[(4 * i + lrow) * IN_F]);
#pragma unroll
        for (int i = 0; i < 2; i++)
            wv[i] = *reinterpret_cast<const float4*>(&wb[(4 * i + lrow) * IN_F]);

        // STS chunk 0 -> buffer 0
#pragma unroll
        for (int i = 0; i < 4; i++) {
            xsw[0][lkq + 0][4 * i + lrow] = xv[i].x;
            xsw[0][lkq + 1][4 * i + lrow] = xv[i].y;
            xsw[0][lkq + 2][4 * i + lrow] = xv[i].z;
            xsw[0][lkq + 3][4 * i + lrow] = xv[i].w;
        }
#pragma unroll
        for (int i = 0; i < 2; i++) {
            wsw[0][lkq + 0][4 * i + lrow] = wv[i].x;
            wsw[0][lkq + 1][4 * i + lrow] = wv[i].y;
            wsw[0][lkq + 2][4 * i + lrow] = wv[i].z;
            wsw[0][lkq + 3][4 * i + lrow] = wv[i].w;
        }
        __syncwarp();

        for (int c = 0; c < NCH; c++) {
            // Prefetch next chunk from gmem while computing this one.
            if (c + 1 < NCH) {
                const int kn = (c + 1) * KB;
#pragma unroll
                for (int i = 0; i < 4; i++)
                    xv[i] = *reinterpret_cast<const float4*>(&xb[(4 * i + lrow) * IN_F + kn]);
#pragma unroll
                for (int i = 0; i < 2; i++)
                    wv[i] = *reinterpret_cast<const float4*>(&wb[(4 * i + lrow) * IN_F + kn]);
            }

            const float (*xc)[XLD] = xsw[c & 1];
            const float (*wc)[WLD] = wsw[c & 1];
#pragma unroll
            for (int k = 0; k < KB; k++) {
                const float2 a = *reinterpret_cast<const float2*>(&xc[k][tn2]);
                const float2 b = *reinterpret_cast<const float2*>(&wc[k][tj2]);
                float p;
                p = a.x * b.x; mx00 = fmaxf(mx00, p); mn00 = fminf(mn00, p);
                p = a.x * b.y; mx01 = fmaxf(mx01, p); mn01 = fminf(mn01, p);
                p = a.y * b.x; mx10 = fmaxf(mx10, p); mn10 = fminf(mn10, p);
                p = a.y * b.y; mx11 = fmaxf(mx11, p); mn11 = fminf(mn11, p);
            }

            // Store prefetched chunk into the other buffer (its previous
            // contents were fully consumed before last iteration's syncwarp).
            if (c + 1 < NCH) {
                const int nb = (c + 1) & 1;
#pragma unroll
                for (int i = 0; i < 4; i++) {
                    xsw[nb][lkq + 0][4 * i + lrow] = xv[i].x;
                    xsw[nb][lkq + 1][4 * i + lrow] = xv[i].y;
                    xsw[nb][lkq + 2][4 * i + lrow] = xv[i].z;
                    xsw[nb][lkq + 3][4 * i + lrow] = xv[i].w;
                }
#pragma unroll
                for (int i = 0; i < 2; i++) {
                    wsw[nb][lkq + 0][4 * i + lrow] = wv[i].x;
                    wsw[nb][lkq + 1][4 * i + lrow] = wv[i].y;
                    wsw[nb][lkq + 2][4 * i + lrow] = wv[i].z;
                    wsw[nb][lkq + 3][4 * i + lrow] = wv[i].w;
                }
            }
            __syncwarp();
        }

        // Epilogue: C = max + min + bias
        const float b0 = bias[j0 + tj2];
        const float b1 = bias[j0 + tj2 + 1];
        float* o0 = &out[(n0 + tn2) * OUT_F + j0 + tj2];
        float* o1 = o0 + OUT_F;
        o0[0] = mx00 + mn00 + b0;
        o0[1] = mx01 + mn01 + b1;
        o1[0] = mx10 + mn10 + b0;
        o1[1] = mx11 + mn11 + b1;
    }
}

extern "C" void kernel_launch(void* const* d_in, const int* in_sizes, int n_in,
                              void* d_out, int out_size)
{
    const float* x    = (const float*)d_in[0];   // [2048, 512]
    const float* w    = (const float*)d_in[1];   // [256, 512]
    const float* bias = (const float*)d_in[2];   // [256]
    float* out        = (float*)d_out;           // [2048, 256]

    mam_kernel<<<GRID, THREADS>>>(x, w, bias, out);
}